// round 16
// baseline (speedup 1.0000x reference)
#include <cuda_runtime.h>
#include <cstdint>
#include <cstddef>

// ---------------- problem constants ----------------
#define T_DIM 4
#define B_DIM 16
#define C_DIM 128
#define E_DIM 256
#define HW_DIM 1024
#define TB_DIM 64
#define BN_EPS 1e-5f
#define LIF_TAU 0.5f

typedef unsigned long long u64;

#define P3_N (E_DIM * C_DIM * 3)
#define P4_N (E_DIM * E_DIM * 3)
#define PR_N (E_DIM * C_DIM)

// ---------------- device scratch (no allocations allowed) ----------------
__device__ float g_mem[(size_t)TB_DIM * E_DIM * HW_DIM];   // conv out NCHW (67 MB)
__device__ float g_spk[(size_t)TB_DIM * E_DIM * HW_DIM];   // lif2 spikes NCHW (67 MB)
// padded conv inputs: [n][c][34 rows][36 cols], zero borders (zero-init, never written)
__device__ float g_padA3[(size_t)TB_DIM * C_DIM * 34 * 36];  // x at col x+1
__device__ float g_padB3[(size_t)TB_DIM * C_DIM * 34 * 36];  // x at col x
__device__ float g_padA4[(size_t)TB_DIM * E_DIM * 34 * 36];
__device__ float g_padB4[(size_t)TB_DIM * E_DIM * 34 * 36];
// packed weights: blk = (e/32)*(CIN/4) + c/4 ; idx = blk*384 + ((c%4)*3+ky)*32 + (e%32)
__device__ ulonglong2 g_w01p3[P3_N];          // {w0dup, w1dup}
__device__ ulonglong2 g_w2p3[P3_N / 2];       // e-pairs {w2dup_e, w2dup_e+1}
__device__ ulonglong2 g_w01p4[P4_N];
__device__ ulonglong2 g_w2p4[P4_N / 2];
__device__ ulonglong2 g_wrp[PR_N / 2];        // res: blk=(e/64)*(CIN/16)+c/16, idx=blk*1024+(c%16)*64+(e%64)
__device__ float      g_bias[3 * E_DIM];

// ---------------- helpers ----------------
union F2U { float2 f2; u64 u; };

__device__ __forceinline__ u64 dup2(float w) {
    F2U u; u.f2 = make_float2(w, w); return u.u;
}
__device__ __forceinline__ void fma2i(u64& acc, u64 a, u64 b) {
    asm("fma.rn.f32x2 %0, %1, %2, %0;" : "+l"(acc) : "l"(a), "l"(b));
}
__device__ __forceinline__ u64 ldsu64(const float* p) {
    return *reinterpret_cast<const u64*>(p);
}
__device__ __forceinline__ ulonglong2 ldsu128(const float* p) {
    return *reinterpret_cast<const ulonglong2*>(p);
}
__device__ __forceinline__ uint32_t smem_u32(const void* p) {
    uint32_t a;
    asm("{ .reg .u64 t; cvta.to.shared.u64 t, %1; cvt.u32.u64 %0, t; }" : "=r"(a) : "l"(p));
    return a;
}
__device__ __forceinline__ void cp16(uint32_t saddr, const void* g) {
    asm volatile("cp.async.cg.shared.global [%0], [%1], 16;" :: "r"(saddr), "l"(g));
}
#define CP_COMMIT() asm volatile("cp.async.commit_group;" ::: "memory")
#define CP_WAIT0()  asm volatile("cp.async.wait_group 0;" ::: "memory")

// ---------------- fold BN + pack weights ----------------
__global__ void fold_pack(const float* __restrict__ w3, const float* __restrict__ g3, const float* __restrict__ v3,
                          const float* __restrict__ w4, const float* __restrict__ g4, const float* __restrict__ v4,
                          const float* __restrict__ wr, const float* __restrict__ gr, const float* __restrict__ vr,
                          ulonglong2* __restrict__ w01p3, ulonglong2* __restrict__ w2p3,
                          ulonglong2* __restrict__ w01p4, ulonglong2* __restrict__ w2p4,
                          ulonglong2* __restrict__ wrp) {
    int i = blockIdx.x * blockDim.x + threadIdx.x;
    if (i < P3_N) {
        int e = i / (C_DIM * 3), r = i % (C_DIM * 3), c = r / 3, ky = r % 3;
        float s = g3[e] * rsqrtf(v3[e] + BN_EPS);
        size_t src = ((size_t)e * C_DIM + c) * 9 + ky * 3;
        float w0 = w3[src] * s, w1 = w3[src + 1] * s, w2 = w3[src + 2] * s;
        size_t blk = (size_t)(e >> 5) * (C_DIM / 4) + (c >> 2);
        size_t idx = blk * 384 + ((c & 3) * 3 + ky) * 32 + (e & 31);
        w01p3[idx] = make_ulonglong2(dup2(w0), dup2(w1));
        ((u64*)w2p3)[idx] = dup2(w2);
    } else if (i < P3_N + P4_N) {
        int j = i - P3_N;
        int e = j / (E_DIM * 3), r = j % (E_DIM * 3), c = r / 3, ky = r % 3;
        float s = g4[e] * rsqrtf(v4[e] + BN_EPS);
        size_t src = ((size_t)e * E_DIM + c) * 9 + ky * 3;
        float w0 = w4[src] * s, w1 = w4[src + 1] * s, w2 = w4[src + 2] * s;
        size_t blk = (size_t)(e >> 5) * (E_DIM / 4) + (c >> 2);
        size_t idx = blk * 384 + ((c & 3) * 3 + ky) * 32 + (e & 31);
        w01p4[idx] = make_ulonglong2(dup2(w0), dup2(w1));
        ((u64*)w2p4)[idx] = dup2(w2);
    } else if (i < P3_N + P4_N + PR_N) {
        int j = i - P3_N - P4_N;
        int e = j / C_DIM, c = j % C_DIM;
        float s = gr[e] * rsqrtf(vr[e] + BN_EPS);
        size_t blk = (size_t)(e >> 6) * (C_DIM / 16) + (c >> 4);
        size_t idx = blk * 1024 + (c & 15) * 64 + (e & 63);
        ((u64*)wrp)[idx] = dup2(wr[(size_t)e * C_DIM + c] * s);
    }
}

__global__ void fold_b(const float* __restrict__ g3, const float* __restrict__ b3,
                       const float* __restrict__ m3, const float* __restrict__ v3,
                       const float* __restrict__ g4, const float* __restrict__ b4,
                       const float* __restrict__ m4, const float* __restrict__ v4,
                       const float* __restrict__ gr, const float* __restrict__ br,
                       const float* __restrict__ mr, const float* __restrict__ vr,
                       float* __restrict__ bf) {
    int e = threadIdx.x;
    if (e >= E_DIM) return;
    if (blockIdx.x == 0)      bf[e]             = b3[e] - m3[e] * (g3[e] * rsqrtf(v3[e] + BN_EPS));
    else if (blockIdx.x == 1) bf[E_DIM + e]     = b4[e] - m4[e] * (g4[e] * rsqrtf(v4[e] + BN_EPS));
    else                      bf[2 * E_DIM + e] = br[e] - mr[e] * (gr[e] * rsqrtf(vr[e] + BN_EPS));
}

// ---------------- LIF -> padded layouts A and B (bit-identical membrane math) ----------------
template <int CIN, int SH>   // SH = 8 + log2(CIN)
__global__ void lifP_kernel(const float4* __restrict__ in,
                            float* __restrict__ padA, float* __restrict__ padB) {
    int gid = blockIdx.x * blockDim.x + threadIdx.x;
    int xq = gid & 7;
    int y  = (gid >> 3) & 31;
    int c  = (gid >> 8) & (CIN - 1);
    int b  = gid >> SH;
    const int tstride = B_DIM * CIN * 256;
    const int base4 = (b * CIN + c) * 256 + y * 8 + xq;
    float m0 = 0.f, m1 = 0.f, m2 = 0.f, m3 = 0.f;
#pragma unroll
    for (int t = 0; t < T_DIM; ++t) {
        float4 v = in[t * tstride + base4];
        m0 = m0 * LIF_TAU + v.x;
        m1 = m1 * LIF_TAU + v.y;
        m2 = m2 * LIF_TAU + v.z;
        m3 = m3 * LIF_TAU + v.w;
        float4 s;
        s.x = (m0 >= 1.0f) ? 1.0f : 0.0f;  if (m0 >= 1.0f) m0 = 0.0f;
        s.y = (m1 >= 1.0f) ? 1.0f : 0.0f;  if (m1 >= 1.0f) m1 = 0.0f;
        s.z = (m2 >= 1.0f) ? 1.0f : 0.0f;  if (m2 >= 1.0f) m2 = 0.0f;
        s.w = (m3 >= 1.0f) ? 1.0f : 0.0f;  if (m3 >= 1.0f) m3 = 0.0f;
        int n = t * B_DIM + b;
        size_t rb = ((size_t)(n * CIN + c) * 34 + (y + 1)) * 36;
        *(float4*)(padB + rb + xq * 4) = s;
        padA[rb + xq * 4 + 1] = s.x;
        padA[rb + xq * 4 + 2] = s.y;
        padA[rb + xq * 4 + 3] = s.z;
        padA[rb + xq * 4 + 4] = s.w;
    }
}

// ---------------- LIF -> NCHW fp32 spikes (for residual addend) ----------------
__global__ void lif_kernel(const float4* __restrict__ in,
                           float4* __restrict__ out, int npt4) {
    int i = blockIdx.x * blockDim.x + threadIdx.x;
    if (i >= npt4) return;
    float m0 = 0.f, m1 = 0.f, m2 = 0.f, m3 = 0.f;
#pragma unroll
    for (int t = 0; t < T_DIM; ++t) {
        float4 v = in[(size_t)t * npt4 + i];
        m0 = m0 * LIF_TAU + v.x;
        m1 = m1 * LIF_TAU + v.y;
        m2 = m2 * LIF_TAU + v.z;
        m3 = m3 * LIF_TAU + v.w;
        float4 s;
        s.x = (m0 >= 1.0f) ? 1.0f : 0.0f;  if (m0 >= 1.0f) m0 = 0.0f;
        s.y = (m1 >= 1.0f) ? 1.0f : 0.0f;  if (m1 >= 1.0f) m1 = 0.0f;
        s.z = (m2 >= 1.0f) ? 1.0f : 0.0f;  if (m2 >= 1.0f) m2 = 0.0f;
        s.w = (m3 >= 1.0f) ? 1.0f : 0.0f;  if (m3 >= 1.0f) m3 = 0.0f;
        out[(size_t)t * npt4 + i] = s;
    }
}

// ---------------- 3x3 conv: 4-row tiles, 128-thr CTAs, occ 5, 2-ring cp.async ----------------
// Thread: 8 e-channels x 4 pixels (2 f32x2 pairs) -> 16 u64 accs (32 regs).
// Per-output FMA chain identical to baseline: (c asc, ky, kx), fma.rn.f32x2.
template <int CIN>
__global__ void __launch_bounds__(128, 5)
conv3k(const float* __restrict__ padA, const float* __restrict__ padB,
       const ulonglong2* __restrict__ w01p, const ulonglong2* __restrict__ w2p,
       const float* __restrict__ bias, float* __restrict__ out) {
    constexpr int CC   = 4;
    constexpr int NST  = CIN / CC;
    constexpr int IN_F = CC * 6 * 36;               // 864 floats per layout (4 rows + halo)
    constexpr int IN_B = IN_F * 4;                  // 3456 B
    constexpr int W01_OFF = 2 * IN_B;               // 6912
    constexpr int W2_OFF  = W01_OFF + 384 * 16;     // 13056
    constexpr int SLOT    = W2_OFF + 192 * 16;      // 16128

    extern __shared__ __align__(16) char dsm[];
    const uint32_t sb = smem_u32(dsm);

    const int n  = blockIdx.z;
    const int eo = blockIdx.y * 32;
    const int r0 = blockIdx.x * 4;
    const int tid = threadIdx.x;
    const int eg  = tid >> 5;          // 4 warps: e-subgroup of 8
    const int pg  = tid & 31;
    const int rr  = pg >> 3;           // row within tile: 0..3
    const int x0  = (pg & 7) << 2;     // col base: 0,4,...,28 (2 pairs)

    const float* baseA = padA + (((size_t)n * CIN) * 34 + r0) * 36;
    const float* baseB = padB + (((size_t)n * CIN) * 34 + r0) * 36;

    u64 acc[8][2];
#pragma unroll
    for (int i = 0; i < 8; ++i) {
        acc[i][0] = 0ull; acc[i][1] = 0ull;
    }

    auto load_stage = [&](int s) {
        if (s >= NST) return;
        const uint32_t slotb = sb + (s & 1) * SLOT;
        const int c0 = s * CC;
        // inputs: 2 layouts x 4ch x 6 rows x 9 cp16 = 432
        for (int k = tid; k < 432; k += 128) {
            int half = (k >= 216) ? 1 : 0;
            int k2 = k - half * 216;
            int cdiv = k2 / 54;
            int rem  = k2 - cdiv * 54;
            int rrow = rem / 9;
            int seg  = rem - rrow * 9;
            const float* src = (half ? baseB : baseA)
                             + (size_t)(c0 + cdiv) * (34 * 36) + rrow * 36 + seg * 4;
            cp16(slotb + half * IN_B + ((cdiv * 6 + rrow) * 36 + seg * 4) * 4, src);
        }
        // weights: contiguous packed blocks (e-block of 32)
        const size_t wb = ((size_t)(eo >> 5) * (CIN / 4) + s);
        const ulonglong2* w01src = w01p + wb * 384;
        const ulonglong2* w2src  = w2p  + wb * 192;
        for (int k = tid; k < 384; k += 128)
            cp16(slotb + W01_OFF + k * 16, w01src + k);
        for (int k = tid; k < 192; k += 128)
            cp16(slotb + W2_OFF + k * 16, w2src + k);
    };

    load_stage(0); CP_COMMIT();

    for (int s = 0; s < NST; ++s) {
        CP_WAIT0();
        __syncthreads();
        load_stage(s + 1); CP_COMMIT();

        const char* slotc = dsm + (s & 1) * SLOT;
        const float* s_in  = (const float*)slotc;
        const float* s_in1 = (const float*)(slotc + IN_B);
        const ulonglong2* s_w01 = (const ulonglong2*)(slotc + W01_OFF);
        const ulonglong2* s_w2  = (const ulonglong2*)(slotc + W2_OFF);

#pragma unroll
        for (int c = 0; c < CC; ++c) {
            const float* rowp  = s_in  + (c * 6 + rr) * 36 + x0;
            const float* row1p = s_in1 + (c * 6 + rr) * 36 + x0;
#pragma unroll
            for (int ky = 0; ky < 3; ++ky) {
                ulonglong2 q01 = ldsu128(rowp);          // q(x0), q(x0+2)
                u64 q2 = ldsu64(rowp + 4);               // q(x0+4)
                ulonglong2 pA = ldsu128(row1p);          // p1 pairs
                u64 p0[2] = {q01.x, q01.y};
                u64 p1[2] = {pA.x, pA.y};
                u64 p2[2] = {q01.y, q2};
                const ulonglong2* w01 = s_w01 + (c * 3 + ky) * 32 + eg * 8;
                const ulonglong2* w2v = s_w2  + (c * 3 + ky) * 16 + eg * 4;
#pragma unroll
                for (int eh = 0; eh < 4; ++eh) {
                    ulonglong2 w2pair = w2v[eh];
#pragma unroll
                    for (int sub = 0; sub < 2; ++sub) {
                        int ee = eh * 2 + sub;
                        ulonglong2 w01e = w01[ee];
                        u64 w2e = sub ? w2pair.y : w2pair.x;
#pragma unroll
                        for (int j = 0; j < 2; ++j) {
                            fma2i(acc[ee][j], w01e.x, p0[j]);
                            fma2i(acc[ee][j], w01e.y, p1[j]);
                            fma2i(acc[ee][j], w2e,    p2[j]);
                        }
                    }
                }
                rowp  += 36;
                row1p += 36;
            }
        }
    }

    // ---- epilogue: + bias, store (order unchanged) ----
#pragma unroll
    for (int ee = 0; ee < 8; ++ee) {
        int e = eo + eg * 8 + ee;
        float b = bias[e];
        size_t obase = ((size_t)n * E_DIM + e) * HW_DIM + (size_t)(r0 + rr) * 32 + x0;
#pragma unroll
        for (int j = 0; j < 2; ++j) {
            F2U u; u.u = acc[ee][j];
            out[obase + 2 * j]     = u.f2.x + b;
            out[obase + 2 * j + 1] = u.f2.y + b;
        }
    }
}

// ---------------- residual 1x1 conv: 2-ring cp.async + add spikes ----------------
__global__ void __launch_bounds__(256, 2)
res1k(const float* __restrict__ x, const ulonglong2* __restrict__ wrp,
      const float* __restrict__ bias, const float* __restrict__ addend,
      float* __restrict__ out) {
    constexpr int CC   = 16;
    constexpr int NST  = C_DIM / CC;
    constexpr int IN_F = CC * 8 * 36;
    constexpr int IN_B = IN_F * 4;                  // 18432 B
    constexpr int SLOT = IN_B + 512 * 16;           // 26624 B

    extern __shared__ __align__(16) char dsm[];
    const uint32_t sb = smem_u32(dsm);

    const int n  = blockIdx.z;
    const int eo = blockIdx.y * 64;
    const int r0 = blockIdx.x * 8;
    const int tid = threadIdx.x;
    const int eg  = tid >> 5;
    const int pg  = tid & 31;
    const int rr  = pg >> 2;
    const int x0  = (pg & 3) << 3;

    const float* basex = x + ((size_t)n * C_DIM) * HW_DIM + r0 * 32;

    u64 acc[8][4];
#pragma unroll
    for (int i = 0; i < 8; ++i)
#pragma unroll
        for (int j = 0; j < 4; ++j) acc[i][j] = 0ull;

    auto load_stage = [&](int s) {
        if (s >= NST) return;
        const uint32_t slotb = sb + (s & 1) * SLOT;
        const int c0 = s * CC;
        for (int k = tid; k < 1024; k += 256) {
            int c = k >> 6;
            int rm = k & 63;
            int rrow = rm >> 3, seg = rm & 7;
            cp16(slotb + ((c * 8 + rrow) * 36 + seg * 4) * 4,
                 basex + (size_t)(c0 + c) * HW_DIM + rrow * 32 + seg * 4);
        }
        const ulonglong2* wsrc = wrp + ((size_t)(eo >> 6) * (C_DIM / 16) + s) * 512;
        for (int k = tid; k < 512; k += 256)
            cp16(slotb + IN_B + k * 16, wsrc + k);
    };

    load_stage(0); CP_COMMIT();

    for (int s = 0; s < NST; ++s) {
        CP_WAIT0();
        __syncthreads();
        load_stage(s + 1); CP_COMMIT();

        const char* slotc = dsm + (s & 1) * SLOT;
        const float* s_in = (const float*)slotc;
        const ulonglong2* s_w = (const ulonglong2*)(slotc + IN_B);
#pragma unroll 4
        for (int c = 0; c < CC; ++c) {
            const float* rowp = s_in + (c * 8 + rr) * 36 + x0;
            ulonglong2 pa = ldsu128(rowp);
            ulonglong2 pb = ldsu128(rowp + 4);
            u64 p[4] = {pa.x, pa.y, pb.x, pb.y};
            const ulonglong2* wv = s_w + c * 32 + eg * 4;
#pragma unroll
            for (int eh = 0; eh < 4; ++eh) {
                ulonglong2 wp2 = wv[eh];
#pragma unroll
                for (int sub = 0; sub < 2; ++sub) {
                    int ee = eh * 2 + sub;
                    u64 w = sub ? wp2.y : wp2.x;
#pragma unroll
                    for (int j = 0; j < 4; ++j) fma2i(acc[ee][j], w, p[j]);
                }
            }
        }
    }

#pragma unroll
    for (int ee = 0; ee < 8; ++ee) {
        int e = eo + eg * 8 + ee;
        float b = bias[e];
        size_t obase = ((size_t)n * E_DIM + e) * HW_DIM + (size_t)(r0 + rr) * 32 + x0;
#pragma unroll
        for (int j = 0; j < 4; ++j) {
            F2U u; u.u = acc[ee][j];
            float lo = u.f2.x + b;
            float hi = u.f2.y + b;
            lo += addend[obase + 2 * j];
            hi += addend[obase + 2 * j + 1];
            out[obase + 2 * j]     = lo;
            out[obase + 2 * j + 1] = hi;
        }
    }
}

// ---------------- launch ----------------
extern "C" void kernel_launch(void* const* d_in, const int* in_sizes, int n_in,
                              void* d_out, int out_size) {
    const float* x  = (const float*)d_in[0];
    const float* w3 = (const float*)d_in[1];
    const float* g3 = (const float*)d_in[2];
    const float* b3 = (const float*)d_in[3];
    const float* m3 = (const float*)d_in[4];
    const float* v3 = (const float*)d_in[5];
    const float* w4 = (const float*)d_in[6];
    const float* g4 = (const float*)d_in[7];
    const float* b4 = (const float*)d_in[8];
    const float* m4 = (const float*)d_in[9];
    const float* v4 = (const float*)d_in[10];
    const float* wr = (const float*)d_in[11];
    const float* gr = (const float*)d_in[12];
    const float* br = (const float*)d_in[13];
    const float* mr = (const float*)d_in[14];
    const float* vr = (const float*)d_in[15];
    float* out = (float*)d_out;

    float *mem, *spk, *pA3, *pB3, *pA4, *pB4, *bias;
    ulonglong2 *w01p3, *w01p4, *w2p3, *w2p4, *wrp;
    cudaGetSymbolAddress((void**)&mem,   g_mem);
    cudaGetSymbolAddress((void**)&spk,   g_spk);
    cudaGetSymbolAddress((void**)&pA3,   g_padA3);
    cudaGetSymbolAddress((void**)&pB3,   g_padB3);
    cudaGetSymbolAddress((void**)&pA4,   g_padA4);
    cudaGetSymbolAddress((void**)&pB4,   g_padB4);
    cudaGetSymbolAddress((void**)&w01p3, g_w01p3);
    cudaGetSymbolAddress((void**)&w2p3,  g_w2p3);
    cudaGetSymbolAddress((void**)&w01p4, g_w01p4);
    cudaGetSymbolAddress((void**)&w2p4,  g_w2p4);
    cudaGetSymbolAddress((void**)&wrp,   g_wrp);
    cudaGetSymbolAddress((void**)&bias,  g_bias);

    const int smem3 = 2 * 16128;   // 32256
    const int smemR = 2 * 26624;   // 53248
    cudaFuncSetAttribute((const void*)conv3k<C_DIM>,
                         cudaFuncAttributeMaxDynamicSharedMemorySize, smem3);
    cudaFuncSetAttribute((const void*)conv3k<E_DIM>,
                         cudaFuncAttributeMaxDynamicSharedMemorySize, smem3);
    cudaFuncSetAttribute((const void*)res1k,
                         cudaFuncAttributeMaxDynamicSharedMemorySize, smemR);

    dim3 cgrid(8, 8, 64);    // rows/4, E/32, images -> 4096 CTAs
    dim3 rgrid(4, 4, 64);
    const int npt_e4 = B_DIM * E_DIM * HW_DIM / 4;

    // 1: fold + pack weights
    fold_pack<<<(P3_N + P4_N + PR_N + 255) / 256, 256>>>(
        w3, g3, v3, w4, g4, v4, wr, gr, vr, w01p3, w2p3, w01p4, w2p4, wrp);
    // 2: fold biases
    fold_b<<<3, E_DIM>>>(g3, b3, m3, v3, g4, b4, m4, v4, gr, br, mr, vr, bias);
    // 3: LIF0 -> padded spikes (C=128)
    lifP_kernel<C_DIM, 15><<<2048, 256>>>((const float4*)x, pA3, pB3);
    // 4: conv3 (128->256) + BN
    conv3k<C_DIM><<<cgrid, 128, smem3>>>(pA3, pB3, w01p3, w2p3, bias, mem);
    // 5: LIF1 -> padded spikes (E=256)
    lifP_kernel<E_DIM, 16><<<4096, 256>>>((const float4*)mem, pA4, pB4);
    // 6: conv4 (256->256) + BN   (ncu -s 5 profiles this launch)
    conv3k<E_DIM><<<cgrid, 128, smem3>>>(pA4, pB4, w01p4, w2p4, bias + E_DIM, mem);
    // 7: LIF2 -> NCHW spikes (residual addend)
    lif_kernel<<<(npt_e4 + 255) / 256, 256>>>((const float4*)mem, (float4*)spk, npt_e4);
    // 8: residual 1x1 + BN + add spikes -> d_out
    res1k<<<rgrid, 256, smemR>>>(x, wrp, bias + 2 * E_DIM, spk, out);
}

// round 17
// speedup vs baseline: 1.0939x; 1.0939x over previous
#include <cuda_runtime.h>
#include <cstdint>
#include <cstddef>

// ---------------- problem constants ----------------
#define T_DIM 4
#define B_DIM 16
#define C_DIM 128
#define E_DIM 256
#define HW_DIM 1024
#define TB_DIM 64
#define BN_EPS 1e-5f
#define LIF_TAU 0.5f
#define NTILES 1024
#define PERSIST_CTAS 304

typedef unsigned long long u64;

#define P3_N (E_DIM * C_DIM * 3)
#define P4_N (E_DIM * E_DIM * 3)
#define PR_N (E_DIM * C_DIM)

// ---------------- device scratch (no allocations allowed) ----------------
__device__ float g_mem[(size_t)TB_DIM * E_DIM * HW_DIM];   // conv out NCHW (67 MB)
__device__ float g_spk[(size_t)TB_DIM * E_DIM * HW_DIM];   // lif2 spikes NCHW (67 MB)
// padded conv inputs: [n][c][34 rows][36 cols], zero borders (zero-init, never written)
__device__ float g_padA3[(size_t)TB_DIM * C_DIM * 34 * 36];  // x at col x+1
__device__ float g_padB3[(size_t)TB_DIM * C_DIM * 34 * 36];  // x at col x
__device__ float g_padA4[(size_t)TB_DIM * E_DIM * 34 * 36];
__device__ float g_padB4[(size_t)TB_DIM * E_DIM * 34 * 36];
// packed weights (round-14 layout): blk = (e/64)*(CIN/4) + c/4
//   idx = blk*768 + ((c%4)*3+ky)*64 + (e%64)
__device__ ulonglong2 g_w01p3[P3_N];          // {w0dup, w1dup}
__device__ ulonglong2 g_w2p3[P3_N / 2];       // e-pairs {w2dup_e, w2dup_e+1}
__device__ ulonglong2 g_w01p4[P4_N];
__device__ ulonglong2 g_w2p4[P4_N / 2];
__device__ ulonglong2 g_wrp[PR_N / 2];        // res: blk=(e/64)*(CIN/16)+c/16, idx=blk*1024+(c%16)*64+(e%64)
__device__ float      g_bias[3 * E_DIM];
__device__ int        g_cnt[2];               // dynamic tile counters (conv3, conv4)

// ---------------- helpers ----------------
union F2U { float2 f2; u64 u; };

__device__ __forceinline__ u64 dup2(float w) {
    F2U u; u.f2 = make_float2(w, w); return u.u;
}
__device__ __forceinline__ void fma2i(u64& acc, u64 a, u64 b) {
    asm("fma.rn.f32x2 %0, %1, %2, %0;" : "+l"(acc) : "l"(a), "l"(b));
}
__device__ __forceinline__ u64 ldsu64(const float* p) {
    return *reinterpret_cast<const u64*>(p);
}
__device__ __forceinline__ ulonglong2 ldsu128(const float* p) {
    return *reinterpret_cast<const ulonglong2*>(p);
}
__device__ __forceinline__ uint32_t smem_u32(const void* p) {
    uint32_t a;
    asm("{ .reg .u64 t; cvta.to.shared.u64 t, %1; cvt.u32.u64 %0, t; }" : "=r"(a) : "l"(p));
    return a;
}
__device__ __forceinline__ void cp16(uint32_t saddr, const void* g) {
    asm volatile("cp.async.cg.shared.global [%0], [%1], 16;" :: "r"(saddr), "l"(g));
}
#define CP_COMMIT() asm volatile("cp.async.commit_group;" ::: "memory")
#define CP_WAIT0()  asm volatile("cp.async.wait_group 0;" ::: "memory")
#define CP_WAIT1()  asm volatile("cp.async.wait_group 1;" ::: "memory")

// ---------------- fold BN + pack weights (round-14 layout) ----------------
__global__ void fold_pack(const float* __restrict__ w3, const float* __restrict__ g3, const float* __restrict__ v3,
                          const float* __restrict__ w4, const float* __restrict__ g4, const float* __restrict__ v4,
                          const float* __restrict__ wr, const float* __restrict__ gr, const float* __restrict__ vr,
                          ulonglong2* __restrict__ w01p3, ulonglong2* __restrict__ w2p3,
                          ulonglong2* __restrict__ w01p4, ulonglong2* __restrict__ w2p4,
                          ulonglong2* __restrict__ wrp) {
    int i = blockIdx.x * blockDim.x + threadIdx.x;
    if (i < P3_N) {
        int e = i / (C_DIM * 3), r = i % (C_DIM * 3), c = r / 3, ky = r % 3;
        float s = g3[e] * rsqrtf(v3[e] + BN_EPS);
        size_t src = ((size_t)e * C_DIM + c) * 9 + ky * 3;
        float w0 = w3[src] * s, w1 = w3[src + 1] * s, w2 = w3[src + 2] * s;
        size_t blk = (size_t)(e >> 6) * (C_DIM / 4) + (c >> 2);
        size_t idx = blk * 768 + ((c & 3) * 3 + ky) * 64 + (e & 63);
        w01p3[idx] = make_ulonglong2(dup2(w0), dup2(w1));
        ((u64*)w2p3)[idx] = dup2(w2);
    } else if (i < P3_N + P4_N) {
        int j = i - P3_N;
        int e = j / (E_DIM * 3), r = j % (E_DIM * 3), c = r / 3, ky = r % 3;
        float s = g4[e] * rsqrtf(v4[e] + BN_EPS);
        size_t src = ((size_t)e * E_DIM + c) * 9 + ky * 3;
        float w0 = w4[src] * s, w1 = w4[src + 1] * s, w2 = w4[src + 2] * s;
        size_t blk = (size_t)(e >> 6) * (E_DIM / 4) + (c >> 2);
        size_t idx = blk * 768 + ((c & 3) * 3 + ky) * 64 + (e & 63);
        w01p4[idx] = make_ulonglong2(dup2(w0), dup2(w1));
        ((u64*)w2p4)[idx] = dup2(w2);
    } else if (i < P3_N + P4_N + PR_N) {
        int j = i - P3_N - P4_N;
        int e = j / C_DIM, c = j % C_DIM;
        float s = gr[e] * rsqrtf(vr[e] + BN_EPS);
        size_t blk = (size_t)(e >> 6) * (C_DIM / 16) + (c >> 4);
        size_t idx = blk * 1024 + (c & 15) * 64 + (e & 63);
        ((u64*)wrp)[idx] = dup2(wr[(size_t)e * C_DIM + c] * s);
    }
}

__global__ void fold_b(const float* __restrict__ g3, const float* __restrict__ b3,
                       const float* __restrict__ m3, const float* __restrict__ v3,
                       const float* __restrict__ g4, const float* __restrict__ b4,
                       const float* __restrict__ m4, const float* __restrict__ v4,
                       const float* __restrict__ gr, const float* __restrict__ br,
                       const float* __restrict__ mr, const float* __restrict__ vr,
                       float* __restrict__ bf, int* __restrict__ cnt) {
    if (blockIdx.x == 0 && threadIdx.x == 0) { cnt[0] = 0; cnt[1] = 0; }
    int e = threadIdx.x;
    if (e >= E_DIM) return;
    if (blockIdx.x == 0)      bf[e]             = b3[e] - m3[e] * (g3[e] * rsqrtf(v3[e] + BN_EPS));
    else if (blockIdx.x == 1) bf[E_DIM + e]     = b4[e] - m4[e] * (g4[e] * rsqrtf(v4[e] + BN_EPS));
    else                      bf[2 * E_DIM + e] = br[e] - mr[e] * (gr[e] * rsqrtf(vr[e] + BN_EPS));
}

// ---------------- LIF -> padded layouts A and B (bit-identical membrane math) ----------------
template <int CIN, int SH>   // SH = 8 + log2(CIN)
__global__ void lifP_kernel(const float4* __restrict__ in,
                            float* __restrict__ padA, float* __restrict__ padB) {
    int gid = blockIdx.x * blockDim.x + threadIdx.x;
    int xq = gid & 7;
    int y  = (gid >> 3) & 31;
    int c  = (gid >> 8) & (CIN - 1);
    int b  = gid >> SH;
    const int tstride = B_DIM * CIN * 256;
    const int base4 = (b * CIN + c) * 256 + y * 8 + xq;
    float m0 = 0.f, m1 = 0.f, m2 = 0.f, m3 = 0.f;
#pragma unroll
    for (int t = 0; t < T_DIM; ++t) {
        float4 v = in[t * tstride + base4];
        m0 = m0 * LIF_TAU + v.x;
        m1 = m1 * LIF_TAU + v.y;
        m2 = m2 * LIF_TAU + v.z;
        m3 = m3 * LIF_TAU + v.w;
        float4 s;
        s.x = (m0 >= 1.0f) ? 1.0f : 0.0f;  if (m0 >= 1.0f) m0 = 0.0f;
        s.y = (m1 >= 1.0f) ? 1.0f : 0.0f;  if (m1 >= 1.0f) m1 = 0.0f;
        s.z = (m2 >= 1.0f) ? 1.0f : 0.0f;  if (m2 >= 1.0f) m2 = 0.0f;
        s.w = (m3 >= 1.0f) ? 1.0f : 0.0f;  if (m3 >= 1.0f) m3 = 0.0f;
        int n = t * B_DIM + b;
        size_t rb = ((size_t)(n * CIN + c) * 34 + (y + 1)) * 36;
        *(float4*)(padB + rb + xq * 4) = s;
        padA[rb + xq * 4 + 1] = s.x;
        padA[rb + xq * 4 + 2] = s.y;
        padA[rb + xq * 4 + 3] = s.z;
        padA[rb + xq * 4 + 4] = s.w;
    }
}

// ---------------- LIF -> NCHW fp32 spikes (for residual addend) ----------------
__global__ void lif_kernel(const float4* __restrict__ in,
                           float4* __restrict__ out, int npt4) {
    int i = blockIdx.x * blockDim.x + threadIdx.x;
    if (i >= npt4) return;
    float m0 = 0.f, m1 = 0.f, m2 = 0.f, m3 = 0.f;
#pragma unroll
    for (int t = 0; t < T_DIM; ++t) {
        float4 v = in[(size_t)t * npt4 + i];
        m0 = m0 * LIF_TAU + v.x;
        m1 = m1 * LIF_TAU + v.y;
        m2 = m2 * LIF_TAU + v.z;
        m3 = m3 * LIF_TAU + v.w;
        float4 s;
        s.x = (m0 >= 1.0f) ? 1.0f : 0.0f;  if (m0 >= 1.0f) m0 = 0.0f;
        s.y = (m1 >= 1.0f) ? 1.0f : 0.0f;  if (m1 >= 1.0f) m1 = 0.0f;
        s.z = (m2 >= 1.0f) ? 1.0f : 0.0f;  if (m2 >= 1.0f) m2 = 0.0f;
        s.w = (m3 >= 1.0f) ? 1.0f : 0.0f;  if (m3 >= 1.0f) m3 = 0.0f;
        out[(size_t)t * npt4 + i] = s;
    }
}

// ---------------- 3x3 conv: PERSISTENT CTAs, dynamic tiles, round-14 per-tile code ----------------
// Tile = (n, eo, r0) decoded exactly like the old grid: x = tile%4 (rows),
// y = (tile/4)%4 (e-block of 64), z = tile/16 (image). Per-tile math bit-identical.
template <int CIN>
__global__ void __launch_bounds__(256, 2)
conv3k(const float* __restrict__ padA, const float* __restrict__ padB,
       const ulonglong2* __restrict__ w01p, const ulonglong2* __restrict__ w2p,
       const float* __restrict__ bias, float* __restrict__ out,
       int* __restrict__ cnt) {
    constexpr int CC   = 4;
    constexpr int NST  = CIN / CC;
    constexpr int IN_F = CC * 10 * 36;              // 1440 floats per layout
    constexpr int IN_B = IN_F * 4;                  // 5760 B
    constexpr int W01_OFF = 2 * IN_B;               // 11520
    constexpr int W2_OFF  = W01_OFF + 768 * 16;     // 23808
    constexpr int SLOT    = W2_OFF + 384 * 16;      // 29952

    extern __shared__ __align__(16) char dsm[];
    const uint32_t sb = smem_u32(dsm);

    const int tid = threadIdx.x;
    const int eg  = tid >> 5;
    const int pg  = tid & 31;
    const int rr  = pg >> 2;
    const int x0  = (pg & 3) << 3;

    __shared__ int s_tile;

    for (;;) {
        if (tid == 0) s_tile = atomicAdd(cnt, 1);
        __syncthreads();
        const int tile = s_tile;
        if (tile >= NTILES) break;

        const int n  = tile >> 4;
        const int eo = ((tile >> 2) & 3) * 64;
        const int r0 = (tile & 3) * 8;

        const float* baseA = padA + (((size_t)n * CIN) * 34 + r0) * 36;
        const float* baseB = padB + (((size_t)n * CIN) * 34 + r0) * 36;

        u64 acc[8][4];
#pragma unroll
        for (int i = 0; i < 8; ++i)
#pragma unroll
            for (int j = 0; j < 4; ++j) acc[i][j] = 0ull;

        auto load_stage = [&](int s) {
            if (s >= NST) return;
            const uint32_t slotb = sb + (s % 3) * SLOT;
            const int c0 = s * CC;
            for (int k = tid; k < 720; k += 256) {
                int half = (k >= 360) ? 1 : 0;
                int k2 = k - half * 360;
                int cdiv = k2 / 90;
                int rem  = k2 - cdiv * 90;
                int rrow = rem / 9;
                int seg  = rem - rrow * 9;
                const float* src = (half ? baseB : baseA)
                                 + (size_t)(c0 + cdiv) * (34 * 36) + rrow * 36 + seg * 4;
                cp16(slotb + half * IN_B + ((cdiv * 10 + rrow) * 36 + seg * 4) * 4, src);
            }
            const size_t wb = ((size_t)(eo >> 6) * (CIN / 4) + s);
            const ulonglong2* w01src = w01p + wb * 768;
            const ulonglong2* w2src  = w2p  + wb * 384;
            for (int k = tid; k < 768; k += 256)
                cp16(slotb + W01_OFF + k * 16, w01src + k);
            for (int k = tid; k < 384; k += 256)
                cp16(slotb + W2_OFF + k * 16, w2src + k);
        };

        load_stage(0); CP_COMMIT();
        load_stage(1); CP_COMMIT();

        for (int s = 0; s < NST; ++s) {
            CP_WAIT1();
            __syncthreads();
            load_stage(s + 2); CP_COMMIT();

            const char* slotc = dsm + (s % 3) * SLOT;
            const float* s_in  = (const float*)slotc;
            const float* s_in1 = (const float*)(slotc + IN_B);
            const ulonglong2* s_w01 = (const ulonglong2*)(slotc + W01_OFF);
            const ulonglong2* s_w2  = (const ulonglong2*)(slotc + W2_OFF);

#pragma unroll
            for (int c = 0; c < CC; ++c) {
                const float* rowp  = s_in  + (c * 10 + rr) * 36 + x0;
                const float* row1p = s_in1 + (c * 10 + rr) * 36 + x0;
#pragma unroll
                for (int ky = 0; ky < 3; ++ky) {
                    ulonglong2 q01 = ldsu128(rowp);
                    ulonglong2 q23 = ldsu128(rowp + 4);
                    u64 q4 = ldsu64(rowp + 8);
                    ulonglong2 pA = ldsu128(row1p);
                    ulonglong2 pB = ldsu128(row1p + 4);
                    u64 p0[4] = {q01.x, q01.y, q23.x, q23.y};
                    u64 p1[4] = {pA.x, pA.y, pB.x, pB.y};
                    u64 p2[4] = {q01.y, q23.x, q23.y, q4};
                    const ulonglong2* w01 = s_w01 + (c * 3 + ky) * 64 + eg * 8;
                    const ulonglong2* w2v = s_w2  + (c * 3 + ky) * 32 + eg * 4;
#pragma unroll
                    for (int eh = 0; eh < 4; ++eh) {
                        ulonglong2 w2pair = w2v[eh];
#pragma unroll
                        for (int sub = 0; sub < 2; ++sub) {
                            int ee = eh * 2 + sub;
                            ulonglong2 w01e = w01[ee];
                            u64 w2e = sub ? w2pair.y : w2pair.x;
#pragma unroll
                            for (int j = 0; j < 4; ++j) {
                                fma2i(acc[ee][j], w01e.x, p0[j]);
                                fma2i(acc[ee][j], w01e.y, p1[j]);
                                fma2i(acc[ee][j], w2e,    p2[j]);
                            }
                        }
                    }
                    rowp  += 36;
                    row1p += 36;
                }
            }
        }

        // ---- epilogue: + bias, store (order unchanged) ----
#pragma unroll
        for (int ee = 0; ee < 8; ++ee) {
            int e = eo + eg * 8 + ee;
            float b = bias[e];
            size_t obase = ((size_t)n * E_DIM + e) * HW_DIM + (size_t)(r0 + rr) * 32 + x0;
#pragma unroll
            for (int j = 0; j < 4; ++j) {
                F2U u; u.u = acc[ee][j];
                out[obase + 2 * j]     = u.f2.x + b;
                out[obase + 2 * j + 1] = u.f2.y + b;
            }
        }
        __syncthreads();   // all warps done with smem slots + s_tile before next claim
    }
}

// ---------------- residual 1x1 conv: 2-ring cp.async + add spikes ----------------
__global__ void __launch_bounds__(256, 2)
res1k(const float* __restrict__ x, const ulonglong2* __restrict__ wrp,
      const float* __restrict__ bias, const float* __restrict__ addend,
      float* __restrict__ out) {
    constexpr int CC   = 16;
    constexpr int NST  = C_DIM / CC;
    constexpr int IN_F = CC * 8 * 36;
    constexpr int IN_B = IN_F * 4;                  // 18432 B
    constexpr int SLOT = IN_B + 512 * 16;           // 26624 B

    extern __shared__ __align__(16) char dsm[];
    const uint32_t sb = smem_u32(dsm);

    const int n  = blockIdx.z;
    const int eo = blockIdx.y * 64;
    const int r0 = blockIdx.x * 8;
    const int tid = threadIdx.x;
    const int eg  = tid >> 5;
    const int pg  = tid & 31;
    const int rr  = pg >> 2;
    const int x0  = (pg & 3) << 3;

    const float* basex = x + ((size_t)n * C_DIM) * HW_DIM + r0 * 32;

    u64 acc[8][4];
#pragma unroll
    for (int i = 0; i < 8; ++i)
#pragma unroll
        for (int j = 0; j < 4; ++j) acc[i][j] = 0ull;

    auto load_stage = [&](int s) {
        if (s >= NST) return;
        const uint32_t slotb = sb + (s & 1) * SLOT;
        const int c0 = s * CC;
        for (int k = tid; k < 1024; k += 256) {
            int c = k >> 6;
            int rm = k & 63;
            int rrow = rm >> 3, seg = rm & 7;
            cp16(slotb + ((c * 8 + rrow) * 36 + seg * 4) * 4,
                 basex + (size_t)(c0 + c) * HW_DIM + rrow * 32 + seg * 4);
        }
        const ulonglong2* wsrc = wrp + ((size_t)(eo >> 6) * (C_DIM / 16) + s) * 512;
        for (int k = tid; k < 512; k += 256)
            cp16(slotb + IN_B + k * 16, wsrc + k);
    };

    load_stage(0); CP_COMMIT();

    for (int s = 0; s < NST; ++s) {
        CP_WAIT0();
        __syncthreads();
        load_stage(s + 1); CP_COMMIT();

        const char* slotc = dsm + (s & 1) * SLOT;
        const float* s_in = (const float*)slotc;
        const ulonglong2* s_w = (const ulonglong2*)(slotc + IN_B);
#pragma unroll 4
        for (int c = 0; c < CC; ++c) {
            const float* rowp = s_in + (c * 8 + rr) * 36 + x0;
            ulonglong2 pa = ldsu128(rowp);
            ulonglong2 pb = ldsu128(rowp + 4);
            u64 p[4] = {pa.x, pa.y, pb.x, pb.y};
            const ulonglong2* wv = s_w + c * 32 + eg * 4;
#pragma unroll
            for (int eh = 0; eh < 4; ++eh) {
                ulonglong2 wp2 = wv[eh];
#pragma unroll
                for (int sub = 0; sub < 2; ++sub) {
                    int ee = eh * 2 + sub;
                    u64 w = sub ? wp2.y : wp2.x;
#pragma unroll
                    for (int j = 0; j < 4; ++j) fma2i(acc[ee][j], w, p[j]);
                }
            }
        }
    }

#pragma unroll
    for (int ee = 0; ee < 8; ++ee) {
        int e = eo + eg * 8 + ee;
        float b = bias[e];
        size_t obase = ((size_t)n * E_DIM + e) * HW_DIM + (size_t)(r0 + rr) * 32 + x0;
#pragma unroll
        for (int j = 0; j < 4; ++j) {
            F2U u; u.u = acc[ee][j];
            float lo = u.f2.x + b;
            float hi = u.f2.y + b;
            lo += addend[obase + 2 * j];
            hi += addend[obase + 2 * j + 1];
            out[obase + 2 * j]     = lo;
            out[obase + 2 * j + 1] = hi;
        }
    }
}

// ---------------- launch ----------------
extern "C" void kernel_launch(void* const* d_in, const int* in_sizes, int n_in,
                              void* d_out, int out_size) {
    const float* x  = (const float*)d_in[0];
    const float* w3 = (const float*)d_in[1];
    const float* g3 = (const float*)d_in[2];
    const float* b3 = (const float*)d_in[3];
    const float* m3 = (const float*)d_in[4];
    const float* v3 = (const float*)d_in[5];
    const float* w4 = (const float*)d_in[6];
    const float* g4 = (const float*)d_in[7];
    const float* b4 = (const float*)d_in[8];
    const float* m4 = (const float*)d_in[9];
    const float* v4 = (const float*)d_in[10];
    const float* wr = (const float*)d_in[11];
    const float* gr = (const float*)d_in[12];
    const float* br = (const float*)d_in[13];
    const float* mr = (const float*)d_in[14];
    const float* vr = (const float*)d_in[15];
    float* out = (float*)d_out;

    float *mem, *spk, *pA3, *pB3, *pA4, *pB4, *bias;
    ulonglong2 *w01p3, *w01p4, *w2p3, *w2p4, *wrp;
    int* cnt;
    cudaGetSymbolAddress((void**)&mem,   g_mem);
    cudaGetSymbolAddress((void**)&spk,   g_spk);
    cudaGetSymbolAddress((void**)&pA3,   g_padA3);
    cudaGetSymbolAddress((void**)&pB3,   g_padB3);
    cudaGetSymbolAddress((void**)&pA4,   g_padA4);
    cudaGetSymbolAddress((void**)&pB4,   g_padB4);
    cudaGetSymbolAddress((void**)&w01p3, g_w01p3);
    cudaGetSymbolAddress((void**)&w2p3,  g_w2p3);
    cudaGetSymbolAddress((void**)&w01p4, g_w01p4);
    cudaGetSymbolAddress((void**)&w2p4,  g_w2p4);
    cudaGetSymbolAddress((void**)&wrp,   g_wrp);
    cudaGetSymbolAddress((void**)&bias,  g_bias);
    cudaGetSymbolAddress((void**)&cnt,   g_cnt);

    const int smem3 = 3 * 29952;   // 89856
    const int smemR = 2 * 26624;   // 53248
    cudaFuncSetAttribute((const void*)conv3k<C_DIM>,
                         cudaFuncAttributeMaxDynamicSharedMemorySize, smem3);
    cudaFuncSetAttribute((const void*)conv3k<E_DIM>,
                         cudaFuncAttributeMaxDynamicSharedMemorySize, smem3);
    cudaFuncSetAttribute((const void*)res1k,
                         cudaFuncAttributeMaxDynamicSharedMemorySize, smemR);

    dim3 rgrid(4, 4, 64);
    const int npt_e4 = B_DIM * E_DIM * HW_DIM / 4;

    // 1: fold + pack weights
    fold_pack<<<(P3_N + P4_N + PR_N + 255) / 256, 256>>>(
        w3, g3, v3, w4, g4, v4, wr, gr, vr, w01p3, w2p3, w01p4, w2p4, wrp);
    // 2: fold biases + reset tile counters (every graph replay)
    fold_b<<<3, E_DIM>>>(g3, b3, m3, v3, g4, b4, m4, v4, gr, br, mr, vr, bias, cnt);
    // 3: LIF0 -> padded spikes (C=128)
    lifP_kernel<C_DIM, 15><<<2048, 256>>>((const float4*)x, pA3, pB3);
    // 4: conv3 (128->256) + BN — persistent, dynamic tiles
    conv3k<C_DIM><<<PERSIST_CTAS, 256, smem3>>>(pA3, pB3, w01p3, w2p3, bias, mem, cnt + 0);
    // 5: LIF1 -> padded spikes (E=256)
    lifP_kernel<E_DIM, 16><<<4096, 256>>>((const float4*)mem, pA4, pB4);
    // 6: conv4 (256->256) + BN — persistent (ncu -s 5 profiles this launch)
    conv3k<E_DIM><<<PERSIST_CTAS, 256, smem3>>>(pA4, pB4, w01p4, w2p4, bias + E_DIM, mem, cnt + 1);
    // 7: LIF2 -> NCHW spikes (residual addend)
    lif_kernel<<<(npt_e4 + 255) / 256, 256>>>((const float4*)mem, (float4*)spk, npt_e4);
    // 8: residual 1x1 + BN + add spikes -> d_out
    res1k<<<rgrid, 256, smemR>>>(x, wrp, bias + 2 * E_DIM, spk, out);
}